// round 6
// baseline (speedup 1.0000x reference)
#include <cuda_runtime.h>
#include <math.h>
#include <stdint.h>

#define BB 4
#define SS 4096
#define EE 512
#define HH 8
#define DD 64
#define WW 256
#define BHN (BB*HH)
#define NEG (-1e30f)

// Scratch: q/k in [b*H+h][s][d]; v TRANSPOSED in [b*H+h][d][s].
__device__ float g_q[(size_t)BHN * SS * DD];
__device__ float g_k[(size_t)BHN * SS * DD];
__device__ float g_vt[(size_t)BHN * DD * SS];

__device__ __forceinline__ uint32_t f2tf(float f) {
    uint32_t u;
    asm("cvt.rna.tf32.f32 %0, %1;" : "=r"(u) : "f"(f));
    return u;
}

// m16n8k8 tf32 mma, fp32 accumulate. A row-major, B col-major.
__device__ __forceinline__ void mma8(float* c,
                                     uint32_t a0, uint32_t a1, uint32_t a2, uint32_t a3,
                                     uint32_t b0, uint32_t b1) {
    asm volatile(
        "mma.sync.aligned.m16n8k8.row.col.f32.tf32.tf32.f32 "
        "{%0,%1,%2,%3},{%4,%5,%6,%7},{%8,%9},{%0,%1,%2,%3};"
        : "+f"(c[0]), "+f"(c[1]), "+f"(c[2]), "+f"(c[3])
        : "r"(a0), "r"(a1), "r"(a2), "r"(a3), "r"(b0), "r"(b1));
}

// ---------------------------------------------------------------------------
// Projection GEMM (tf32, R4-proven): C = (X @ W^T + bias) * scale.
// vt=0: write Out[b*H+h][s][d]; vt=1: write transposed Out[b*H+h][d][s].
// ---------------------------------------------------------------------------
__global__ __launch_bounds__(256, 2)
void proj_mma(const float* __restrict__ X,
              const float* __restrict__ Wm,
              const float* __restrict__ bias,
              float* __restrict__ Out,
              float scale, int vt)
{
    __shared__ uint32_t Ap[8][4][32][4];   // 16KB: A fragments
    __shared__ uint32_t Bp[16][4][32][2];  // 16KB: B fragments

    const int tid = threadIdx.x;
    const int lane = tid & 31;
    const int w = tid >> 5;
    const int wm = w >> 2;
    const int wn = w & 3;
    const int m0 = blockIdx.y * 128;
    const int n0 = blockIdx.x * 128;
    const int g = lane >> 2;
    const int t = lane & 3;

    float acc[4][4][4];
#pragma unroll
    for (int mt = 0; mt < 4; mt++)
#pragma unroll
        for (int nt = 0; nt < 4; nt++)
#pragma unroll
            for (int i = 0; i < 4; i++) acc[mt][nt][i] = 0.f;

    for (int k0 = 0; k0 < EE; k0 += 32) {
        __syncthreads();
#pragma unroll
        for (int p = 0; p < 4; p++) {
            int pair = w * 4 + p;
            int mt = pair >> 2, s = pair & 3;
            const float* base = X + (size_t)(m0 + mt * 16 + g) * EE + k0 + s * 8 + t;
            uint4 u;
            u.x = f2tf(base[0]);
            u.y = f2tf(base[8 * EE]);
            u.z = f2tf(base[4]);
            u.w = f2tf(base[8 * EE + 4]);
            *(uint4*)&Ap[mt][s][lane][0] = u;
        }
#pragma unroll
        for (int p = 0; p < 8; p++) {
            int pair = w * 8 + p;
            int nt = pair >> 2, s = pair & 3;
            const float* base = Wm + (size_t)(n0 + nt * 8 + g) * EE + k0 + s * 8 + t;
            uint2 u;
            u.x = f2tf(base[0]);
            u.y = f2tf(base[4]);
            *(uint2*)&Bp[nt][s][lane][0] = u;
        }
        __syncthreads();

#pragma unroll
        for (int s = 0; s < 4; s++) {
            uint2 bf[4];
#pragma unroll
            for (int nt = 0; nt < 4; nt++)
                bf[nt] = *(const uint2*)&Bp[wn * 4 + nt][s][lane][0];
#pragma unroll
            for (int mt = 0; mt < 4; mt++) {
                uint4 af = *(const uint4*)&Ap[wm * 4 + mt][s][lane][0];
#pragma unroll
                for (int nt = 0; nt < 4; nt++)
                    mma8(acc[mt][nt], af.x, af.y, af.z, af.w, bf[nt].x, bf[nt].y);
            }
        }
    }

    // Epilogue: bias + scale, permuted store.
#pragma unroll
    for (int mt = 0; mt < 4; mt++) {
        int r0 = m0 + wm * 64 + mt * 16 + g;
        int r1 = r0 + 8;
        int b0i = r0 >> 12, s0i = r0 & (SS - 1);
        int b1i = r1 >> 12, s1i = r1 & (SS - 1);
#pragma unroll
        for (int nt = 0; nt < 4; nt++) {
            int n = n0 + wn * 32 + nt * 8 + 2 * t;
            int h = n >> 6, d = n & 63;
            float2 bi = *(const float2*)(bias + n);
            float v00 = (acc[mt][nt][0] + bi.x) * scale;
            float v01 = (acc[mt][nt][1] + bi.y) * scale;
            float v10 = (acc[mt][nt][2] + bi.x) * scale;
            float v11 = (acc[mt][nt][3] + bi.y) * scale;
            if (!vt) {
                *(float2*)(&Out[((size_t)(b0i * HH + h) * SS + s0i) * DD + d]) =
                    make_float2(v00, v01);
                *(float2*)(&Out[((size_t)(b1i * HH + h) * SS + s1i) * DD + d]) =
                    make_float2(v10, v11);
            } else {
                // Transposed: Out[(bh*64 + d)*SS + s]
                size_t c0 = ((size_t)((b0i * HH + h) * 64 + d)) * SS;
                size_t c1 = ((size_t)((b1i * HH + h) * 64 + d)) * SS;
                Out[c0 + s0i]      = v00;
                Out[c0 + SS + s0i] = v01;
                Out[c1 + s1i]      = v10;
                Out[c1 + SS + s1i] = v11;
            }
        }
    }
}

// ---------------------------------------------------------------------------
// Band attention (tf32 mma.sync), ZERO shared memory, zero block syncs.
// 4 independent warps; warp w owns q rows [i0+16w, i0+16w+16).
// d-permutation: fragment k-index t <-> phys col 8s+2t, t+4 <-> 8s+2t+1
//   -> every K fragment is one LDG.64 (Q built with same permutation).
// j-permutation pi(s,t)=8s+2t: PV A-fragment == QK C-fragment registers
//   (a0,a1,a2,a3 = sc[s][0],sc[s][2],sc[s][1],sc[s][3]); V^T fragment is
//   one LDG.64 from the transposed V.
// K/V/P fed as raw f32 bits (tf32 truncation).
// ---------------------------------------------------------------------------
__global__ __launch_bounds__(128)
void attn_mma(float* __restrict__ out)
{
    const int bh = blockIdx.y;
    const int bb = bh >> 3;
    const int hh = bh & 7;
    const int i0 = blockIdx.x * 64;
    const int tid = threadIdx.x;
    const int w = tid >> 5;
    const int lane = tid & 31;
    const int g = lane >> 2;
    const int t = lane & 3;

    const float* qg  = g_q  + (size_t)bh * SS * DD;
    const float* kgp = g_k  + (size_t)bh * SS * DD;
    const float* vtg = g_vt + (size_t)bh * DD * SS;

    // Q fragments (permuted d), built once.
    uint32_t qa[8][4];
    {
        const float* qb = qg + (size_t)(i0 + 16 * w) * DD;
#pragma unroll
        for (int s = 0; s < 8; s++) {
            float2 x0 = *(const float2*)(qb + (size_t)g * DD + 8 * s + 2 * t);
            float2 x1 = *(const float2*)(qb + (size_t)(g + 8) * DD + 8 * s + 2 * t);
            qa[s][0] = f2tf(x0.x);   // A[g][k=t]       <-> phys col 8s+2t
            qa[s][2] = f2tf(x0.y);   // A[g][k=t+4]     <-> phys col 8s+2t+1
            qa[s][1] = f2tf(x1.x);   // A[g+8][k=t]
            qa[s][3] = f2tf(x1.y);   // A[g+8][k=t+4]
        }
    }

    float oacc[8][4];
#pragma unroll
    for (int nt = 0; nt < 8; nt++)
#pragma unroll
        for (int i = 0; i < 4; i++) oacc[nt][i] = 0.f;
    float mA = NEG, mB = NEG, lA = 0.f, lB = 0.f;

    const int rA = 16 * w + g;   // first owned row (tile-local)

    for (int ch = 0; ch < 9; ch++) {
        int j0 = i0 - WW + ch * 64;
        if (j0 < 0 || j0 >= SS) continue;   // uniform per block

        const float* kp = kgp + (size_t)j0 * DD;
        const float* vp = vtg + j0;

        // QK: S = Q @ K^T; K fragments straight from global (LDG.64).
        float sc[8][4];
#pragma unroll
        for (int nt = 0; nt < 8; nt++)
#pragma unroll
            for (int i = 0; i < 4; i++) sc[nt][i] = 0.f;
#pragma unroll
        for (int s = 0; s < 8; s++) {
#pragma unroll
            for (int nt = 0; nt < 8; nt++) {
                uint2 bv = *(const uint2*)(kp + (size_t)(nt * 8 + g) * DD + 8 * s + 2 * t);
                mma8(sc[nt], qa[s][0], qa[s][1], qa[s][2], qa[s][3], bv.x, bv.y);
            }
        }

        // Band mask (chunk 0: col >= row; chunk 8: col <= row)
        if (ch == 0) {
#pragma unroll
            for (int nt = 0; nt < 8; nt++) {
                int c0 = 8 * nt + 2 * t;
                if (c0     < rA)     sc[nt][0] = NEG;
                if (c0 + 1 < rA)     sc[nt][1] = NEG;
                if (c0     < rA + 8) sc[nt][2] = NEG;
                if (c0 + 1 < rA + 8) sc[nt][3] = NEG;
            }
        } else if (ch == 8) {
#pragma unroll
            for (int nt = 0; nt < 8; nt++) {
                int c0 = 8 * nt + 2 * t;
                if (c0     > rA)     sc[nt][0] = NEG;
                if (c0 + 1 > rA)     sc[nt][1] = NEG;
                if (c0     > rA + 8) sc[nt][2] = NEG;
                if (c0 + 1 > rA + 8) sc[nt][3] = NEG;
            }
        }

        // Online softmax (rows rA, rA+8; quad reduction over t)
        float vA = NEG, vB = NEG;
#pragma unroll
        for (int nt = 0; nt < 8; nt++) {
            vA = fmaxf(vA, fmaxf(sc[nt][0], sc[nt][1]));
            vB = fmaxf(vB, fmaxf(sc[nt][2], sc[nt][3]));
        }
        vA = fmaxf(vA, __shfl_xor_sync(0xffffffffu, vA, 1));
        vA = fmaxf(vA, __shfl_xor_sync(0xffffffffu, vA, 2));
        vB = fmaxf(vB, __shfl_xor_sync(0xffffffffu, vB, 1));
        vB = fmaxf(vB, __shfl_xor_sync(0xffffffffu, vB, 2));
        float mAn = fmaxf(mA, vA), mBn = fmaxf(mB, vB);
        float sumA = 0.f, sumB = 0.f;
#pragma unroll
        for (int nt = 0; nt < 8; nt++) {
            sc[nt][0] = __expf(sc[nt][0] - mAn);
            sc[nt][1] = __expf(sc[nt][1] - mAn);
            sc[nt][2] = __expf(sc[nt][2] - mBn);
            sc[nt][3] = __expf(sc[nt][3] - mBn);
            sumA += sc[nt][0] + sc[nt][1];
            sumB += sc[nt][2] + sc[nt][3];
        }
        sumA += __shfl_xor_sync(0xffffffffu, sumA, 1);
        sumA += __shfl_xor_sync(0xffffffffu, sumA, 2);
        sumB += __shfl_xor_sync(0xffffffffu, sumB, 1);
        sumB += __shfl_xor_sync(0xffffffffu, sumB, 2);
        float fA = __expf(mA - mAn), fB = __expf(mB - mBn);
        mA = mAn; mB = mBn;
        lA = lA * fA + sumA;
        lB = lB * fB + sumB;
#pragma unroll
        for (int nt = 0; nt < 8; nt++) {
            oacc[nt][0] *= fA; oacc[nt][1] *= fA;
            oacc[nt][2] *= fB; oacc[nt][3] *= fB;
        }

        // PV: O += P @ V. P stays in registers (C-frag == A-frag under pi);
        // V^T fragments straight from global (LDG.64, row d, cols j0+8s+2t..+1).
#pragma unroll
        for (int s = 0; s < 8; s++) {
            uint32_t a0 = __float_as_uint(sc[s][0]);   // P[g][8s+2t]
            uint32_t a1 = __float_as_uint(sc[s][2]);   // P[g+8][8s+2t]
            uint32_t a2 = __float_as_uint(sc[s][1]);   // P[g][8s+2t+1]
            uint32_t a3 = __float_as_uint(sc[s][3]);   // P[g+8][8s+2t+1]
#pragma unroll
            for (int nt = 0; nt < 8; nt++) {
                uint2 bv = *(const uint2*)(vp + (size_t)(nt * 8 + g) * SS + 8 * s + 2 * t);
                mma8(oacc[nt], a0, a1, a2, a3, bv.x, bv.y);
            }
        }
    }

    // Epilogue: out_flat[s*2048 + b*512 + h*64 + d]
    float iA = 1.f / lA, iB = 1.f / lB;
    size_t baseA = (size_t)(i0 + rA) * 2048 + (size_t)(bb * 512 + hh * 64);
    size_t baseB = baseA + (size_t)8 * 2048;
#pragma unroll
    for (int nt = 0; nt < 8; nt++) {
        int d = 8 * nt + 2 * t;
        float2 o;
        o.x = oacc[nt][0] * iA; o.y = oacc[nt][1] * iA;
        *(float2*)(out + baseA + d) = o;
        o.x = oacc[nt][2] * iB; o.y = oacc[nt][3] * iB;
        *(float2*)(out + baseB + d) = o;
    }
}

// ---------------------------------------------------------------------------
extern "C" void kernel_launch(void* const* d_in, const int* in_sizes, int n_in,
                              void* d_out, int out_size)
{
    (void)in_sizes; (void)n_in; (void)out_size;
    const float* query = (const float*)d_in[0];
    const float* key   = (const float*)d_in[1];
    const float* value = (const float*)d_in[2];
    const float* Wq = (const float*)d_in[4];
    const float* bq = (const float*)d_in[5];
    const float* Wk = (const float*)d_in[6];
    const float* bk = (const float*)d_in[7];
    const float* Wv = (const float*)d_in[8];
    const float* bv = (const float*)d_in[9];
    float* out = (float*)d_out;

    float *qp, *kp, *vtp;
    cudaGetSymbolAddress((void**)&qp,  g_q);
    cudaGetSymbolAddress((void**)&kp,  g_k);
    cudaGetSymbolAddress((void**)&vtp, g_vt);

    dim3 gp(EE / 128, (BB * SS) / 128);   // (4, 128)
    proj_mma<<<gp, 256>>>(query, Wq, bq, qp,  0.125f, 0);  // 1/sqrt(64)
    proj_mma<<<gp, 256>>>(key,   Wk, bk, kp,  1.0f,   0);
    proj_mma<<<gp, 256>>>(value, Wv, bv, vtp, 1.0f,   1);  // transposed

    attn_mma<<<dim3(SS / 64, BHN), 128>>>(out);
}

// round 7
// speedup vs baseline: 1.2042x; 1.2042x over previous
#include <cuda_runtime.h>
#include <math.h>
#include <stdint.h>

#define BB 4
#define SS 4096
#define EE 512
#define HH 8
#define DD 64
#define WW 256
#define BHN (BB*HH)
#define NEG (-1e30f)

// Scratch q/k/v in [b*H+h][s][d] layout (q pre-scaled by 1/sqrt(D))
__device__ float g_q[(size_t)BHN * SS * DD];
__device__ float g_k[(size_t)BHN * SS * DD];
__device__ float g_v[(size_t)BHN * SS * DD];

__device__ __forceinline__ uint32_t f2tf(float f) {
    uint32_t u;
    asm("cvt.rna.tf32.f32 %0, %1;" : "=r"(u) : "f"(f));
    return u;
}

// m16n8k8 tf32 mma, fp32 accumulate. A row-major, B col-major.
__device__ __forceinline__ void mma8(float* c,
                                     uint32_t a0, uint32_t a1, uint32_t a2, uint32_t a3,
                                     uint32_t b0, uint32_t b1) {
    asm volatile(
        "mma.sync.aligned.m16n8k8.row.col.f32.tf32.tf32.f32 "
        "{%0,%1,%2,%3},{%4,%5,%6,%7},{%8,%9},{%0,%1,%2,%3};"
        : "+f"(c[0]), "+f"(c[1]), "+f"(c[2]), "+f"(c[3])
        : "r"(a0), "r"(a1), "r"(a2), "r"(a3), "r"(b0), "r"(b1));
}

// ---------------------------------------------------------------------------
// Projection GEMM (tf32, R4-proven): C = (X @ W^T + bias) * scale
// -> Out[b*H+h][s][d]  (m = b*S+s, n = h*64+d)
// ---------------------------------------------------------------------------
__global__ __launch_bounds__(256, 2)
void proj_mma(const float* __restrict__ X,
              const float* __restrict__ Wm,
              const float* __restrict__ bias,
              float* __restrict__ Out,
              float scale)
{
    __shared__ uint32_t Ap[8][4][32][4];
    __shared__ uint32_t Bp[16][4][32][2];

    const int tid = threadIdx.x;
    const int lane = tid & 31;
    const int w = tid >> 5;
    const int wm = w >> 2;
    const int wn = w & 3;
    const int m0 = blockIdx.y * 128;
    const int n0 = blockIdx.x * 128;
    const int g = lane >> 2;
    const int t = lane & 3;

    float acc[4][4][4];
#pragma unroll
    for (int mt = 0; mt < 4; mt++)
#pragma unroll
        for (int nt = 0; nt < 4; nt++)
#pragma unroll
            for (int i = 0; i < 4; i++) acc[mt][nt][i] = 0.f;

    for (int k0 = 0; k0 < EE; k0 += 32) {
        __syncthreads();
#pragma unroll
        for (int p = 0; p < 4; p++) {
            int pair = w * 4 + p;
            int mt = pair >> 2, s = pair & 3;
            const float* base = X + (size_t)(m0 + mt * 16 + g) * EE + k0 + s * 8 + t;
            uint4 u;
            u.x = f2tf(base[0]);
            u.y = f2tf(base[8 * EE]);
            u.z = f2tf(base[4]);
            u.w = f2tf(base[8 * EE + 4]);
            *(uint4*)&Ap[mt][s][lane][0] = u;
        }
#pragma unroll
        for (int p = 0; p < 8; p++) {
            int pair = w * 8 + p;
            int nt = pair >> 2, s = pair & 3;
            const float* base = Wm + (size_t)(n0 + nt * 8 + g) * EE + k0 + s * 8 + t;
            uint2 u;
            u.x = f2tf(base[0]);
            u.y = f2tf(base[4]);
            *(uint2*)&Bp[nt][s][lane][0] = u;
        }
        __syncthreads();

#pragma unroll
        for (int s = 0; s < 4; s++) {
            uint2 bf[4];
#pragma unroll
            for (int nt = 0; nt < 4; nt++)
                bf[nt] = *(const uint2*)&Bp[wn * 4 + nt][s][lane][0];
#pragma unroll
            for (int mt = 0; mt < 4; mt++) {
                uint4 af = *(const uint4*)&Ap[wm * 4 + mt][s][lane][0];
#pragma unroll
                for (int nt = 0; nt < 4; nt++)
                    mma8(acc[mt][nt], af.x, af.y, af.z, af.w, bf[nt].x, bf[nt].y);
            }
        }
    }

#pragma unroll
    for (int mt = 0; mt < 4; mt++) {
        int r0 = m0 + wm * 64 + mt * 16 + g;
        int r1 = r0 + 8;
        int b0i = r0 >> 12, s0i = r0 & (SS - 1);
        int b1i = r1 >> 12, s1i = r1 & (SS - 1);
#pragma unroll
        for (int nt = 0; nt < 4; nt++) {
            int n = n0 + wn * 32 + nt * 8 + 2 * t;
            int h = n >> 6, d = n & 63;
            float2 bi = *(const float2*)(bias + n);
            float2 o;
            o.x = (acc[mt][nt][0] + bi.x) * scale;
            o.y = (acc[mt][nt][1] + bi.y) * scale;
            *(float2*)(&Out[((size_t)(b0i * HH + h) * SS + s0i) * DD + d]) = o;
            o.x = (acc[mt][nt][2] + bi.x) * scale;
            o.y = (acc[mt][nt][3] + bi.y) * scale;
            *(float2*)(&Out[((size_t)(b1i * HH + h) * SS + s1i) * DD + d]) = o;
        }
    }
}

// ---------------------------------------------------------------------------
// Band attention (tf32 mma.sync): 64-query tile per (b,h), 9 key chunks.
// 4 warps, warp w owns q rows [16w, 16w+16).
// d-permutation: QK fragment k=t <-> phys d col 8s+2t, k=t+4 <-> 8s+2t+1
//   -> K slot fill = one coalesced LDG.64 per lane; Q regs built likewise.
// j-permutation pi(s,t)=8s+2t on PV's k axis: the QK C-fragment registers
//   ARE the PV A-fragment (a0,a1,a2,a3 = sc[s][0],sc[s][2],sc[s][1],sc[s][3]);
//   V staged so slot (nt,s) lane holds V[8s+2t][8nt+g], V[8s+2t+1][8nt+g].
// P never touches memory. smem = 32KB, 2 syncs/chunk, zero bank conflicts.
// ---------------------------------------------------------------------------
__global__ __launch_bounds__(128)
void attn_mma(float* __restrict__ out)
{
    __shared__ uint32_t Kf[8][8][32][2];   // 16KB: K fragments
    __shared__ uint32_t Vf[8][8][32][2];   // 16KB: V fragments

    const int bh = blockIdx.y;
    const int bb = bh >> 3;
    const int hh = bh & 7;
    const int i0 = blockIdx.x * 64;
    const int tid = threadIdx.x;
    const int w = tid >> 5;
    const int lane = tid & 31;
    const int g = lane >> 2;
    const int t = lane & 3;

    const float* qg = g_q + (size_t)bh * SS * DD;
    const float* kg = g_k + (size_t)bh * SS * DD;
    const float* vg = g_v + (size_t)bh * SS * DD;

    // Q fragments (permuted d), built once, held in registers.
    uint32_t qa[8][4];
    {
        const float* qb = qg + (size_t)(i0 + 16 * w) * DD;
#pragma unroll
        for (int s = 0; s < 8; s++) {
            float2 x0 = *(const float2*)(qb + (size_t)g * DD + 8 * s + 2 * t);
            float2 x1 = *(const float2*)(qb + (size_t)(g + 8) * DD + 8 * s + 2 * t);
            qa[s][0] = f2tf(x0.x);   // A[g][k=t]     <-> d col 8s+2t
            qa[s][2] = f2tf(x0.y);   // A[g][k=t+4]   <-> d col 8s+2t+1
            qa[s][1] = f2tf(x1.x);   // A[g+8][k=t]
            qa[s][3] = f2tf(x1.y);   // A[g+8][k=t+4]
        }
    }

    float oacc[8][4];
#pragma unroll
    for (int nt = 0; nt < 8; nt++)
#pragma unroll
        for (int i = 0; i < 4; i++) oacc[nt][i] = 0.f;
    float mA = NEG, mB = NEG, lA = 0.f, lB = 0.f;

    const int rA = 16 * w + g;   // first owned row (tile-local)

    for (int ch = 0; ch < 9; ch++) {
        int j0 = i0 - WW + ch * 64;
        if (j0 < 0 || j0 >= SS) continue;   // uniform per block

        __syncthreads();   // prior QK/PV smem reads done before restage

        const float* kp = kg + (size_t)j0 * DD;
        const float* vp = vg + (size_t)j0 * DD;
        // K slots: 64 (nt,s), 16 per warp; one LDG.64 + one STS.64 per lane.
        // b0 = K[8nt+g][8s+2t], b1 = K[8nt+g][8s+2t+1]  (permuted d).
#pragma unroll
        for (int p = 0; p < 16; p++) {
            int pair = w * 16 + p;
            int nt = pair >> 3, s = pair & 7;
            float2 x = *(const float2*)(kp + (size_t)(nt * 8 + g) * DD + 8 * s + 2 * t);
            uint2 u;
            u.x = f2tf(x.x);
            u.y = f2tf(x.y);
            *(uint2*)&Kf[nt][s][lane][0] = u;
        }
        // V slots: b0 = V[8s+2t][8nt+g], b1 = V[8s+2t+1][8nt+g]  (permuted j).
#pragma unroll
        for (int p = 0; p < 16; p++) {
            int pair = w * 16 + p;
            int nt = pair >> 3, s = pair & 7;
            const float* base = vp + (size_t)(8 * s + 2 * t) * DD + nt * 8 + g;
            uint2 u;
            u.x = f2tf(base[0]);
            u.y = f2tf(base[DD]);
            *(uint2*)&Vf[nt][s][lane][0] = u;
        }
        __syncthreads();

        // QK: S = Q @ K^T (16 rows x 64 cols per warp)
        float sc[8][4];
#pragma unroll
        for (int nt = 0; nt < 8; nt++)
#pragma unroll
            for (int i = 0; i < 4; i++) sc[nt][i] = 0.f;
#pragma unroll
        for (int s = 0; s < 8; s++) {
#pragma unroll
            for (int nt = 0; nt < 8; nt++) {
                uint2 bv = *(const uint2*)&Kf[nt][s][lane][0];
                mma8(sc[nt], qa[s][0], qa[s][1], qa[s][2], qa[s][3], bv.x, bv.y);
            }
        }

        // Band mask (chunk 0: col >= row; chunk 8: col <= row)
        if (ch == 0) {
#pragma unroll
            for (int nt = 0; nt < 8; nt++) {
                int c0 = 8 * nt + 2 * t;
                if (c0     < rA)     sc[nt][0] = NEG;
                if (c0 + 1 < rA)     sc[nt][1] = NEG;
                if (c0     < rA + 8) sc[nt][2] = NEG;
                if (c0 + 1 < rA + 8) sc[nt][3] = NEG;
            }
        } else if (ch == 8) {
#pragma unroll
            for (int nt = 0; nt < 8; nt++) {
                int c0 = 8 * nt + 2 * t;
                if (c0     > rA)     sc[nt][0] = NEG;
                if (c0 + 1 > rA)     sc[nt][1] = NEG;
                if (c0     > rA + 8) sc[nt][2] = NEG;
                if (c0 + 1 > rA + 8) sc[nt][3] = NEG;
            }
        }

        // Online softmax (rows rA, rA+8; quad reduction over t)
        float vA = NEG, vB = NEG;
#pragma unroll
        for (int nt = 0; nt < 8; nt++) {
            vA = fmaxf(vA, fmaxf(sc[nt][0], sc[nt][1]));
            vB = fmaxf(vB, fmaxf(sc[nt][2], sc[nt][3]));
        }
        vA = fmaxf(vA, __shfl_xor_sync(0xffffffffu, vA, 1));
        vA = fmaxf(vA, __shfl_xor_sync(0xffffffffu, vA, 2));
        vB = fmaxf(vB, __shfl_xor_sync(0xffffffffu, vB, 1));
        vB = fmaxf(vB, __shfl_xor_sync(0xffffffffu, vB, 2));
        float mAn = fmaxf(mA, vA), mBn = fmaxf(mB, vB);
        float sumA = 0.f, sumB = 0.f;
#pragma unroll
        for (int nt = 0; nt < 8; nt++) {
            sc[nt][0] = __expf(sc[nt][0] - mAn);
            sc[nt][1] = __expf(sc[nt][1] - mAn);
            sc[nt][2] = __expf(sc[nt][2] - mBn);
            sc[nt][3] = __expf(sc[nt][3] - mBn);
            sumA += sc[nt][0] + sc[nt][1];
            sumB += sc[nt][2] + sc[nt][3];
        }
        sumA += __shfl_xor_sync(0xffffffffu, sumA, 1);
        sumA += __shfl_xor_sync(0xffffffffu, sumA, 2);
        sumB += __shfl_xor_sync(0xffffffffu, sumB, 1);
        sumB += __shfl_xor_sync(0xffffffffu, sumB, 2);
        float fA = __expf(mA - mAn), fB = __expf(mB - mBn);
        mA = mAn; mB = mBn;
        lA = lA * fA + sumA;
        lB = lB * fB + sumB;
#pragma unroll
        for (int nt = 0; nt < 8; nt++) {
            oacc[nt][0] *= fA; oacc[nt][1] *= fA;
            oacc[nt][2] *= fB; oacc[nt][3] *= fB;
        }

        // PV: O += P @ V. P stays in registers (C-frag == A-frag under pi).
#pragma unroll
        for (int s = 0; s < 8; s++) {
            uint32_t a0 = f2tf(sc[s][0]);   // P[g][8s+2t]
            uint32_t a1 = f2tf(sc[s][2]);   // P[g+8][8s+2t]
            uint32_t a2 = f2tf(sc[s][1]);   // P[g][8s+2t+1]
            uint32_t a3 = f2tf(sc[s][3]);   // P[g+8][8s+2t+1]
#pragma unroll
            for (int nt = 0; nt < 8; nt++) {
                uint2 bv = *(const uint2*)&Vf[nt][s][lane][0];
                mma8(oacc[nt], a0, a1, a2, a3, bv.x, bv.y);
            }
        }
    }

    // Epilogue: out_flat[s*2048 + b*512 + h*64 + d]
    float iA = 1.f / lA, iB = 1.f / lB;
    size_t baseA = (size_t)(i0 + rA) * 2048 + (size_t)(bb * 512 + hh * 64);
    size_t baseB = baseA + (size_t)8 * 2048;
#pragma unroll
    for (int nt = 0; nt < 8; nt++) {
        int d = 8 * nt + 2 * t;
        float2 o;
        o.x = oacc[nt][0] * iA; o.y = oacc[nt][1] * iA;
        *(float2*)(out + baseA + d) = o;
        o.x = oacc[nt][2] * iB; o.y = oacc[nt][3] * iB;
        *(float2*)(out + baseB + d) = o;
    }
}

// ---------------------------------------------------------------------------
extern "C" void kernel_launch(void* const* d_in, const int* in_sizes, int n_in,
                              void* d_out, int out_size)
{
    (void)in_sizes; (void)n_in; (void)out_size;
    const float* query = (const float*)d_in[0];
    const float* key   = (const float*)d_in[1];
    const float* value = (const float*)d_in[2];
    const float* Wq = (const float*)d_in[4];
    const float* bq = (const float*)d_in[5];
    const float* Wk = (const float*)d_in[6];
    const float* bk = (const float*)d_in[7];
    const float* Wv = (const float*)d_in[8];
    const float* bv = (const float*)d_in[9];
    float* out = (float*)d_out;

    float *qp, *kp, *vp;
    cudaGetSymbolAddress((void**)&qp, g_q);
    cudaGetSymbolAddress((void**)&kp, g_k);
    cudaGetSymbolAddress((void**)&vp, g_v);

    dim3 gp(EE / 128, (BB * SS) / 128);   // (4, 128)
    proj_mma<<<gp, 256>>>(query, Wq, bq, qp, 0.125f);  // 1/sqrt(64)
    proj_mma<<<gp, 256>>>(key,   Wk, bk, kp, 1.0f);
    proj_mma<<<gp, 256>>>(value, Wv, bv, vp, 1.0f);

    attn_mma<<<dim3(SS / 64, BHN), 128>>>(out);
}

// round 8
// speedup vs baseline: 1.4620x; 1.2141x over previous
#include <cuda_runtime.h>
#include <math.h>
#include <stdint.h>

#define BB 4
#define SS 4096
#define EE 512
#define HH 8
#define DD 64
#define WW 256
#define BHN (BB*HH)
#define NEG (-1e30f)

// Scratch q/k/v in [b*H+h][s][d] layout (q pre-scaled by 1/sqrt(D))
__device__ float g_q[(size_t)BHN * SS * DD];
__device__ float g_k[(size_t)BHN * SS * DD];
__device__ float g_v[(size_t)BHN * SS * DD];

__device__ __forceinline__ uint32_t f2tf(float f) {
    uint32_t u;
    asm("cvt.rna.tf32.f32 %0, %1;" : "=r"(u) : "f"(f));
    return u;
}

// m16n8k8 tf32 mma, fp32 accumulate. A row-major, B col-major.
__device__ __forceinline__ void mma8(float* c,
                                     uint32_t a0, uint32_t a1, uint32_t a2, uint32_t a3,
                                     uint32_t b0, uint32_t b1) {
    asm volatile(
        "mma.sync.aligned.m16n8k8.row.col.f32.tf32.tf32.f32 "
        "{%0,%1,%2,%3},{%4,%5,%6,%7},{%8,%9},{%0,%1,%2,%3};"
        : "+f"(c[0]), "+f"(c[1]), "+f"(c[2]), "+f"(c[3])
        : "r"(a0), "r"(a1), "r"(a2), "r"(a3), "r"(b0), "r"(b1));
}

// ---------------------------------------------------------------------------
// Fused projection GEMMs (tf32): one launch, blockIdx.z in {0,1,2} = Q,K,V.
// C = (X @ W^T + bias) * scale -> Out[b*H+h][s][d]  (m = b*S+s, n = h*64+d).
// k-permutation: fragment k=t <-> phys col k0+8s+2t, k=t+4 <-> k0+8s+2t+1
//   (consistent for A and B) -> all staging loads are LDG.64.
// Register-prefetch double buffering: next chunk's LDGs issue before the
//   current chunk's mma compute, hiding global latency under HMMA.
// ---------------------------------------------------------------------------
__global__ __launch_bounds__(256, 2)
void proj_mma(const float* __restrict__ Xq, const float* __restrict__ Xk,
              const float* __restrict__ Xv,
              const float* __restrict__ Wq, const float* __restrict__ Wk,
              const float* __restrict__ Wv,
              const float* __restrict__ bq, const float* __restrict__ bk,
              const float* __restrict__ bv,
              float* __restrict__ Oq, float* __restrict__ Ok,
              float* __restrict__ Ov)
{
    __shared__ uint32_t Ap[8][4][32][4];   // 16KB: A fragments
    __shared__ uint32_t Bp[16][4][32][2];  // 16KB: B fragments

    const int z = blockIdx.z;
    const float* X    = (z == 0) ? Xq : (z == 1) ? Xk : Xv;
    const float* Wm   = (z == 0) ? Wq : (z == 1) ? Wk : Wv;
    const float* bias = (z == 0) ? bq : (z == 1) ? bk : bv;
    float*       Out  = (z == 0) ? Oq : (z == 1) ? Ok : Ov;
    const float scale = (z == 0) ? 0.125f : 1.0f;

    const int tid = threadIdx.x;
    const int lane = tid & 31;
    const int w = tid >> 5;
    const int wm = w >> 2;
    const int wn = w & 3;
    const int m0 = blockIdx.y * 128;
    const int n0 = blockIdx.x * 128;
    const int g = lane >> 2;
    const int t = lane & 3;

    float acc[4][4][4];
#pragma unroll
    for (int mt = 0; mt < 4; mt++)
#pragma unroll
        for (int nt = 0; nt < 4; nt++)
#pragma unroll
            for (int i = 0; i < 4; i++) acc[mt][nt][i] = 0.f;

    // Per-thread base pointers for its fragment slots (k-chunk varying part
    // added in the loop).  A: 4 (mt,s) slots; B: 8 (nt,s) slots.
    const float* aBase[4];
    const float* bBase[8];
#pragma unroll
    for (int p = 0; p < 4; p++) {
        int pair = w * 4 + p;
        int mt = pair >> 2, s = pair & 3;
        aBase[p] = X + (size_t)(m0 + mt * 16 + g) * EE + 8 * s + 2 * t;
    }
#pragma unroll
    for (int p = 0; p < 8; p++) {
        int pair = w * 8 + p;
        int nt = pair >> 2, s = pair & 3;
        bBase[p] = Wm + (size_t)(n0 + nt * 8 + g) * EE + 8 * s + 2 * t;
    }

    // Prefetch registers for one k-chunk.
    float2 pa0[4], pa1[4], pb[8];
#pragma unroll
    for (int p = 0; p < 4; p++) {
        pa0[p] = *(const float2*)(aBase[p]);
        pa1[p] = *(const float2*)(aBase[p] + 8 * EE);
    }
#pragma unroll
    for (int p = 0; p < 8; p++) pb[p] = *(const float2*)(bBase[p]);

    for (int kc = 0; kc < 16; kc++) {
        // Store prefetched chunk into fragment slots (conflict-free STS).
#pragma unroll
        for (int p = 0; p < 4; p++) {
            int pair = w * 4 + p;
            int mt = pair >> 2, s = pair & 3;
            uint4 u;
            u.x = f2tf(pa0[p].x);   // a0 = A[g][k=t]
            u.y = f2tf(pa1[p].x);   // a1 = A[g+8][k=t]
            u.z = f2tf(pa0[p].y);   // a2 = A[g][k=t+4]
            u.w = f2tf(pa1[p].y);   // a3 = A[g+8][k=t+4]
            *(uint4*)&Ap[mt][s][lane][0] = u;
        }
#pragma unroll
        for (int p = 0; p < 8; p++) {
            int pair = w * 8 + p;
            int nt = pair >> 2, s = pair & 3;
            uint2 u;
            u.x = f2tf(pb[p].x);    // b0 = B[n][k=t]
            u.y = f2tf(pb[p].y);    // b1 = B[n][k=t+4]
            *(uint2*)&Bp[nt][s][lane][0] = u;
        }
        __syncthreads();

        // Prefetch next chunk (LDGs overlap the mma compute below).
        if (kc + 1 < 16) {
            const int koff = (kc + 1) * 32;
#pragma unroll
            for (int p = 0; p < 4; p++) {
                pa0[p] = *(const float2*)(aBase[p] + koff);
                pa1[p] = *(const float2*)(aBase[p] + koff + 8 * EE);
            }
#pragma unroll
            for (int p = 0; p < 8; p++)
                pb[p] = *(const float2*)(bBase[p] + koff);
        }

        // Compute.
#pragma unroll
        for (int s = 0; s < 4; s++) {
            uint2 bf[4];
#pragma unroll
            for (int nt = 0; nt < 4; nt++)
                bf[nt] = *(const uint2*)&Bp[wn * 4 + nt][s][lane][0];
#pragma unroll
            for (int mt = 0; mt < 4; mt++) {
                uint4 af = *(const uint4*)&Ap[wm * 4 + mt][s][lane][0];
#pragma unroll
                for (int nt = 0; nt < 4; nt++)
                    mma8(acc[mt][nt], af.x, af.y, af.z, af.w, bf[nt].x, bf[nt].y);
            }
        }
        __syncthreads();   // compute done before next store
    }

    // Epilogue: bias + scale, permuted store.
#pragma unroll
    for (int mt = 0; mt < 4; mt++) {
        int r0 = m0 + wm * 64 + mt * 16 + g;
        int r1 = r0 + 8;
        int b0i = r0 >> 12, s0i = r0 & (SS - 1);
        int b1i = r1 >> 12, s1i = r1 & (SS - 1);
#pragma unroll
        for (int nt = 0; nt < 4; nt++) {
            int n = n0 + wn * 32 + nt * 8 + 2 * t;
            int h = n >> 6, d = n & 63;
            float2 bi = *(const float2*)(bias + n);
            float2 o;
            o.x = (acc[mt][nt][0] + bi.x) * scale;
            o.y = (acc[mt][nt][1] + bi.y) * scale;
            *(float2*)(&Out[((size_t)(b0i * HH + h) * SS + s0i) * DD + d]) = o;
            o.x = (acc[mt][nt][2] + bi.x) * scale;
            o.y = (acc[mt][nt][3] + bi.y) * scale;
            *(float2*)(&Out[((size_t)(b1i * HH + h) * SS + s1i) * DD + d]) = o;
        }
    }
}

// ---------------------------------------------------------------------------
// Band attention (tf32 mma.sync) — unchanged from R7 (193.5us, known good).
// ---------------------------------------------------------------------------
__global__ __launch_bounds__(128)
void attn_mma(float* __restrict__ out)
{
    __shared__ uint32_t Kf[8][8][32][2];
    __shared__ uint32_t Vf[8][8][32][2];

    const int bh = blockIdx.y;
    const int bb = bh >> 3;
    const int hh = bh & 7;
    const int i0 = blockIdx.x * 64;
    const int tid = threadIdx.x;
    const int w = tid >> 5;
    const int lane = tid & 31;
    const int g = lane >> 2;
    const int t = lane & 3;

    const float* qg = g_q + (size_t)bh * SS * DD;
    const float* kg = g_k + (size_t)bh * SS * DD;
    const float* vg = g_v + (size_t)bh * SS * DD;

    uint32_t qa[8][4];
    {
        const float* qb = qg + (size_t)(i0 + 16 * w) * DD;
#pragma unroll
        for (int s = 0; s < 8; s++) {
            float2 x0 = *(const float2*)(qb + (size_t)g * DD + 8 * s + 2 * t);
            float2 x1 = *(const float2*)(qb + (size_t)(g + 8) * DD + 8 * s + 2 * t);
            qa[s][0] = f2tf(x0.x);
            qa[s][2] = f2tf(x0.y);
            qa[s][1] = f2tf(x1.x);
            qa[s][3] = f2tf(x1.y);
        }
    }

    float oacc[8][4];
#pragma unroll
    for (int nt = 0; nt < 8; nt++)
#pragma unroll
        for (int i = 0; i < 4; i++) oacc[nt][i] = 0.f;
    float mA = NEG, mB = NEG, lA = 0.f, lB = 0.f;

    const int rA = 16 * w + g;

    for (int ch = 0; ch < 9; ch++) {
        int j0 = i0 - WW + ch * 64;
        if (j0 < 0 || j0 >= SS) continue;

        __syncthreads();

        const float* kp = kg + (size_t)j0 * DD;
        const float* vp = vg + (size_t)j0 * DD;
#pragma unroll
        for (int p = 0; p < 16; p++) {
            int pair = w * 16 + p;
            int nt = pair >> 3, s = pair & 7;
            float2 x = *(const float2*)(kp + (size_t)(nt * 8 + g) * DD + 8 * s + 2 * t);
            uint2 u;
            u.x = f2tf(x.x);
            u.y = f2tf(x.y);
            *(uint2*)&Kf[nt][s][lane][0] = u;
        }
#pragma unroll
        for (int p = 0; p < 16; p++) {
            int pair = w * 16 + p;
            int nt = pair >> 3, s = pair & 7;
            const float* base = vp + (size_t)(8 * s + 2 * t) * DD + nt * 8 + g;
            uint2 u;
            u.x = f2tf(base[0]);
            u.y = f2tf(base[DD]);
            *(uint2*)&Vf[nt][s][lane][0] = u;
        }
        __syncthreads();

        float sc[8][4];
#pragma unroll
        for (int nt = 0; nt < 8; nt++)
#pragma unroll
            for (int i = 0; i < 4; i++) sc[nt][i] = 0.f;
#pragma unroll
        for (int s = 0; s < 8; s++) {
#pragma unroll
            for (int nt = 0; nt < 8; nt++) {
                uint2 bv = *(const uint2*)&Kf[nt][s][lane][0];
                mma8(sc[nt], qa[s][0], qa[s][1], qa[s][2], qa[s][3], bv.x, bv.y);
            }
        }

        if (ch == 0) {
#pragma unroll
            for (int nt = 0; nt < 8; nt++) {
                int c0 = 8 * nt + 2 * t;
                if (c0     < rA)     sc[nt][0] = NEG;
                if (c0 + 1 < rA)     sc[nt][1] = NEG;
                if (c0     < rA + 8) sc[nt][2] = NEG;
                if (c0 + 1 < rA + 8) sc[nt][3] = NEG;
            }
        } else if (ch == 8) {
#pragma unroll
            for (int nt = 0; nt < 8; nt++) {
                int c0 = 8 * nt + 2 * t;
                if (c0     > rA)     sc[nt][0] = NEG;
                if (c0 + 1 > rA)     sc[nt][1] = NEG;
                if (c0     > rA + 8) sc[nt][2] = NEG;
                if (c0 + 1 > rA + 8) sc[nt][3] = NEG;
            }
        }

        float vA = NEG, vB = NEG;
#pragma unroll
        for (int nt = 0; nt < 8; nt++) {
            vA = fmaxf(vA, fmaxf(sc[nt][0], sc[nt][1]));
            vB = fmaxf(vB, fmaxf(sc[nt][2], sc[nt][3]));
        }
        vA = fmaxf(vA, __shfl_xor_sync(0xffffffffu, vA, 1));
        vA = fmaxf(vA, __shfl_xor_sync(0xffffffffu, vA, 2));
        vB = fmaxf(vB, __shfl_xor_sync(0xffffffffu, vB, 1));
        vB = fmaxf(vB, __shfl_xor_sync(0xffffffffu, vB, 2));
        float mAn = fmaxf(mA, vA), mBn = fmaxf(mB, vB);
        float sumA = 0.f, sumB = 0.f;
#pragma unroll
        for (int nt = 0; nt < 8; nt++) {
            sc[nt][0] = __expf(sc[nt][0] - mAn);
            sc[nt][1] = __expf(sc[nt][1] - mAn);
            sc[nt][2] = __expf(sc[nt][2] - mBn);
            sc[nt][3] = __expf(sc[nt][3] - mBn);
            sumA += sc[nt][0] + sc[nt][1];
            sumB += sc[nt][2] + sc[nt][3];
        }
        sumA += __shfl_xor_sync(0xffffffffu, sumA, 1);
        sumA += __shfl_xor_sync(0xffffffffu, sumA, 2);
        sumB += __shfl_xor_sync(0xffffffffu, sumB, 1);
        sumB += __shfl_xor_sync(0xffffffffu, sumB, 2);
        float fA = __expf(mA - mAn), fB = __expf(mB - mBn);
        mA = mAn; mB = mBn;
        lA = lA * fA + sumA;
        lB = lB * fB + sumB;
#pragma unroll
        for (int nt = 0; nt < 8; nt++) {
            oacc[nt][0] *= fA; oacc[nt][1] *= fA;
            oacc[nt][2] *= fB; oacc[nt][3] *= fB;
        }

#pragma unroll
        for (int s = 0; s < 8; s++) {
            uint32_t a0 = f2tf(sc[s][0]);
            uint32_t a1 = f2tf(sc[s][2]);
            uint32_t a2 = f2tf(sc[s][1]);
            uint32_t a3 = f2tf(sc[s][3]);
#pragma unroll
            for (int nt = 0; nt < 8; nt++) {
                uint2 bv = *(const uint2*)&Vf[nt][s][lane][0];
                mma8(oacc[nt], a0, a1, a2, a3, bv.x, bv.y);
            }
        }
    }

    float iA = 1.f / lA, iB = 1.f / lB;
    size_t baseA = (size_t)(i0 + rA) * 2048 + (size_t)(bb * 512 + hh * 64);
    size_t baseB = baseA + (size_t)8 * 2048;
#pragma unroll
    for (int nt = 0; nt < 8; nt++) {
        int d = 8 * nt + 2 * t;
        float2 o;
        o.x = oacc[nt][0] * iA; o.y = oacc[nt][1] * iA;
        *(float2*)(out + baseA + d) = o;
        o.x = oacc[nt][2] * iB; o.y = oacc[nt][3] * iB;
        *(float2*)(out + baseB + d) = o;
    }
}

// ---------------------------------------------------------------------------
extern "C" void kernel_launch(void* const* d_in, const int* in_sizes, int n_in,
                              void* d_out, int out_size)
{
    (void)in_sizes; (void)n_in; (void)out_size;
    const float* query = (const float*)d_in[0];
    const float* key   = (const float*)d_in[1];
    const float* value = (const float*)d_in[2];
    const float* Wq = (const float*)d_in[4];
    const float* bq = (const float*)d_in[5];
    const float* Wk = (const float*)d_in[6];
    const float* bk = (const float*)d_in[7];
    const float* Wv = (const float*)d_in[8];
    const float* bv = (const float*)d_in[9];
    float* out = (float*)d_out;

    float *qp, *kp, *vp;
    cudaGetSymbolAddress((void**)&qp, g_q);
    cudaGetSymbolAddress((void**)&kp, g_k);
    cudaGetSymbolAddress((void**)&vp, g_v);

    dim3 gp(EE / 128, (BB * SS) / 128, 3);   // (4, 128, 3) — fused Q/K/V
    proj_mma<<<gp, 256>>>(query, key, value, Wq, Wk, Wv, bq, bk, bv, qp, kp, vp);

    attn_mma<<<dim3(SS / 64, BHN), 128>>>(out);
}

// round 9
// speedup vs baseline: 1.5717x; 1.0750x over previous
#include <cuda_runtime.h>
#include <math.h>
#include <stdint.h>

#define BB 4
#define SS 4096
#define EE 512
#define HH 8
#define DD 64
#define WW 256
#define BHN (BB*HH)
#define NEG (-1e30f)

// Scratch q/k/v in [b*H+h][s][d] layout (q pre-scaled by 1/sqrt(D))
__device__ float g_q[(size_t)BHN * SS * DD];
__device__ float g_k[(size_t)BHN * SS * DD];
__device__ float g_v[(size_t)BHN * SS * DD];

__device__ __forceinline__ uint32_t f2tf(float f) {
    uint32_t u;
    asm("cvt.rna.tf32.f32 %0, %1;" : "=r"(u) : "f"(f));
    return u;
}

// m16n8k8 tf32 mma, fp32 accumulate. A row-major, B col-major.
__device__ __forceinline__ void mma8(float* c,
                                     uint32_t a0, uint32_t a1, uint32_t a2, uint32_t a3,
                                     uint32_t b0, uint32_t b1) {
    asm volatile(
        "mma.sync.aligned.m16n8k8.row.col.f32.tf32.tf32.f32 "
        "{%0,%1,%2,%3},{%4,%5,%6,%7},{%8,%9},{%0,%1,%2,%3};"
        : "+f"(c[0]), "+f"(c[1]), "+f"(c[2]), "+f"(c[3])
        : "r"(a0), "r"(a1), "r"(a2), "r"(a3), "r"(b0), "r"(b1));
}

// ---------------------------------------------------------------------------
// Fused projection GEMMs (tf32): blockIdx.z in {0,1,2} = Q,K,V.
// C = (X @ W^T + bias) * scale -> Out[b*H+h][s][d].
// k-permuted LDG.64 staging + register prefetch (R8-proven).
// NEW: B fragments pair-packed (adjacent nt) -> LDS.128 reads.
// ---------------------------------------------------------------------------
__global__ __launch_bounds__(256, 2)
void proj_mma(const float* __restrict__ Xq, const float* __restrict__ Xk,
              const float* __restrict__ Xv,
              const float* __restrict__ Wq, const float* __restrict__ Wk,
              const float* __restrict__ Wv,
              const float* __restrict__ bq, const float* __restrict__ bk,
              const float* __restrict__ bv,
              float* __restrict__ Oq, float* __restrict__ Ok,
              float* __restrict__ Ov)
{
    __shared__ uint32_t Ap[8][4][32][4];   // 16KB: A fragments
    __shared__ uint32_t Bp[8][4][32][4];   // 16KB: B fragment PAIRS (np = nt/2)

    const int z = blockIdx.z;
    const float* X    = (z == 0) ? Xq : (z == 1) ? Xk : Xv;
    const float* Wm   = (z == 0) ? Wq : (z == 1) ? Wk : Wv;
    const float* bias = (z == 0) ? bq : (z == 1) ? bk : bv;
    float*       Out  = (z == 0) ? Oq : (z == 1) ? Ok : Ov;
    const float scale = (z == 0) ? 0.125f : 1.0f;

    const int tid = threadIdx.x;
    const int lane = tid & 31;
    const int w = tid >> 5;
    const int wm = w >> 2;
    const int wn = w & 3;
    const int m0 = blockIdx.y * 128;
    const int n0 = blockIdx.x * 128;
    const int g = lane >> 2;
    const int t = lane & 3;

    float acc[4][4][4];
#pragma unroll
    for (int mt = 0; mt < 4; mt++)
#pragma unroll
        for (int nt = 0; nt < 4; nt++)
#pragma unroll
            for (int i = 0; i < 4; i++) acc[mt][nt][i] = 0.f;

    // Per-thread fragment-slot base pointers (k-chunk offset added in loop).
    const float* aBase[4];   // A: 4 (mt,s) slots per warp
    const float* bBase[4];   // B: 4 (np,s) packed slots per warp
#pragma unroll
    for (int p = 0; p < 4; p++) {
        int pair = w * 4 + p;
        int mt = pair >> 2, s = pair & 3;
        aBase[p] = X + (size_t)(m0 + mt * 16 + g) * EE + 8 * s + 2 * t;
    }
#pragma unroll
    for (int p = 0; p < 4; p++) {
        int slot = w * 4 + p;
        int np = slot >> 2, s = slot & 3;
        bBase[p] = Wm + (size_t)(n0 + np * 16 + g) * EE + 8 * s + 2 * t;
    }

    // Prefetch registers for one k-chunk.
    float2 pa0[4], pa1[4], pb0[4], pb1[4];
#pragma unroll
    for (int p = 0; p < 4; p++) {
        pa0[p] = *(const float2*)(aBase[p]);
        pa1[p] = *(const float2*)(aBase[p] + 8 * EE);
        pb0[p] = *(const float2*)(bBase[p]);
        pb1[p] = *(const float2*)(bBase[p] + 8 * EE);
    }

    for (int kc = 0; kc < 16; kc++) {
        // Store prefetched chunk into fragment slots (conflict-free STS.128).
#pragma unroll
        for (int p = 0; p < 4; p++) {
            int pair = w * 4 + p;
            int mt = pair >> 2, s = pair & 3;
            uint4 u;
            u.x = f2tf(pa0[p].x);   // a0 = A[g][k=t]
            u.y = f2tf(pa1[p].x);   // a1 = A[g+8][k=t]
            u.z = f2tf(pa0[p].y);   // a2 = A[g][k=t+4]
            u.w = f2tf(pa1[p].y);   // a3 = A[g+8][k=t+4]
            *(uint4*)&Ap[mt][s][lane][0] = u;
        }
#pragma unroll
        for (int p = 0; p < 4; p++) {
            int slot = w * 4 + p;
            int np = slot >> 2, s = slot & 3;
            uint4 u;
            u.x = f2tf(pb0[p].x);   // b0 of nt=2np   (row 16np+g)
            u.y = f2tf(pb0[p].y);   // b1 of nt=2np
            u.z = f2tf(pb1[p].x);   // b0 of nt=2np+1 (row 16np+8+g)
            u.w = f2tf(pb1[p].y);   // b1 of nt=2np+1
            *(uint4*)&Bp[np][s][lane][0] = u;
        }
        __syncthreads();

        // Prefetch next chunk (LDGs overlap mma compute below).
        if (kc + 1 < 16) {
            const int koff = (kc + 1) * 32;
#pragma unroll
            for (int p = 0; p < 4; p++) {
                pa0[p] = *(const float2*)(aBase[p] + koff);
                pa1[p] = *(const float2*)(aBase[p] + koff + 8 * EE);
                pb0[p] = *(const float2*)(bBase[p] + koff);
                pb1[p] = *(const float2*)(bBase[p] + koff + 8 * EE);
            }
        }

        // Compute.
#pragma unroll
        for (int s = 0; s < 4; s++) {
            uint4 bf0 = *(const uint4*)&Bp[wn * 2 + 0][s][lane][0];
            uint4 bf1 = *(const uint4*)&Bp[wn * 2 + 1][s][lane][0];
#pragma unroll
            for (int mt = 0; mt < 4; mt++) {
                uint4 af = *(const uint4*)&Ap[wm * 4 + mt][s][lane][0];
                mma8(acc[mt][0], af.x, af.y, af.z, af.w, bf0.x, bf0.y);
                mma8(acc[mt][1], af.x, af.y, af.z, af.w, bf0.z, bf0.w);
                mma8(acc[mt][2], af.x, af.y, af.z, af.w, bf1.x, bf1.y);
                mma8(acc[mt][3], af.x, af.y, af.z, af.w, bf1.z, bf1.w);
            }
        }
        __syncthreads();   // compute done before next store
    }

    // Epilogue: bias + scale, permuted store.
#pragma unroll
    for (int mt = 0; mt < 4; mt++) {
        int r0 = m0 + wm * 64 + mt * 16 + g;
        int r1 = r0 + 8;
        int b0i = r0 >> 12, s0i = r0 & (SS - 1);
        int b1i = r1 >> 12, s1i = r1 & (SS - 1);
#pragma unroll
        for (int nt = 0; nt < 4; nt++) {
            int n = n0 + wn * 32 + nt * 8 + 2 * t;
            int h = n >> 6, d = n & 63;
            float2 bi = *(const float2*)(bias + n);
            float2 o;
            o.x = (acc[mt][nt][0] + bi.x) * scale;
            o.y = (acc[mt][nt][1] + bi.y) * scale;
            *(float2*)(&Out[((size_t)(b0i * HH + h) * SS + s0i) * DD + d]) = o;
            o.x = (acc[mt][nt][2] + bi.x) * scale;
            o.y = (acc[mt][nt][3] + bi.y) * scale;
            *(float2*)(&Out[((size_t)(b1i * HH + h) * SS + s1i) * DD + d]) = o;
        }
    }
}

// ---------------------------------------------------------------------------
// Band attention (tf32 mma.sync), R7 design + LDS.128 pair-packing:
// K and V fragments for adjacent nt are packed into one uint4 slot, so every
// operand read in QK and PV is a single conflict-free LDS.128.
// Q in registers (d-permuted); P never touches memory (C-frag == A-frag
// under the j-permutation pi(s,t)=8s+2t).
// ---------------------------------------------------------------------------
__global__ __launch_bounds__(128)
void attn_mma(float* __restrict__ out)
{
    __shared__ uint32_t Kf[8][4][32][4];   // 16KB: [s][np][lane][4]
    __shared__ uint32_t Vf[8][4][32][4];   // 16KB: [s][np][lane][4]

    const int bh = blockIdx.y;
    const int bb = bh >> 3;
    const int hh = bh & 7;
    const int i0 = blockIdx.x * 64;
    const int tid = threadIdx.x;
    const int w = tid >> 5;
    const int lane = tid & 31;
    const int g = lane >> 2;
    const int t = lane & 3;

    const float* qg = g_q + (size_t)bh * SS * DD;
    const float* kg = g_k + (size_t)bh * SS * DD;
    const float* vg = g_v + (size_t)bh * SS * DD;

    // Q fragments (permuted d), built once, held in registers.
    uint32_t qa[8][4];
    {
        const float* qb = qg + (size_t)(i0 + 16 * w) * DD;
#pragma unroll
        for (int s = 0; s < 8; s++) {
            float2 x0 = *(const float2*)(qb + (size_t)g * DD + 8 * s + 2 * t);
            float2 x1 = *(const float2*)(qb + (size_t)(g + 8) * DD + 8 * s + 2 * t);
            qa[s][0] = f2tf(x0.x);
            qa[s][2] = f2tf(x0.y);
            qa[s][1] = f2tf(x1.x);
            qa[s][3] = f2tf(x1.y);
        }
    }

    float oacc[8][4];
#pragma unroll
    for (int nt = 0; nt < 8; nt++)
#pragma unroll
        for (int i = 0; i < 4; i++) oacc[nt][i] = 0.f;
    float mA = NEG, mB = NEG, lA = 0.f, lB = 0.f;

    const int rA = 16 * w + g;   // first owned row (tile-local)

    for (int ch = 0; ch < 9; ch++) {
        int j0 = i0 - WW + ch * 64;
        if (j0 < 0 || j0 >= SS) continue;   // uniform per block

        __syncthreads();   // prior QK/PV smem reads done before restage

        const float* kp = kg + (size_t)j0 * DD;
        const float* vp = vg + (size_t)j0 * DD;

        // K packed slots: 32 (s,np), 8 per warp.  uint4 =
        // (K[16np+g][8s+2t], K[16np+g][8s+2t+1],
        //  K[16np+8+g][8s+2t], K[16np+8+g][8s+2t+1])  -> 2 LDG.64 + STS.128.
#pragma unroll
        for (int p = 0; p < 8; p++) {
            int slot = w * 8 + p;        // 0..31
            int np = slot >> 3, s = slot & 7;
            const float* r0 = kp + (size_t)(16 * np + g) * DD + 8 * s + 2 * t;
            float2 x0 = *(const float2*)r0;
            float2 x1 = *(const float2*)(r0 + 8 * DD);
            uint4 u;
            u.x = f2tf(x0.x); u.y = f2tf(x0.y);
            u.z = f2tf(x1.x); u.w = f2tf(x1.y);
            *(uint4*)&Kf[s][np][lane][0] = u;
        }
        // V packed slots: uint4 =
        // (V[8s+2t][16np+g], V[8s+2t+1][16np+g],
        //  V[8s+2t][16np+8+g], V[8s+2t+1][16np+8+g])   -> 4 LDG.32 + STS.128.
#pragma unroll
        for (int p = 0; p < 8; p++) {
            int slot = w * 8 + p;
            int np = slot >> 3, s = slot & 7;
            const float* r0 = vp + (size_t)(8 * s + 2 * t) * DD;
            const float* r1 = r0 + DD;
            uint4 u;
            u.x = f2tf(r0[16 * np + g]);
            u.y = f2tf(r1[16 * np + g]);
            u.z = f2tf(r0[16 * np + 8 + g]);
            u.w = f2tf(r1[16 * np + 8 + g]);
            *(uint4*)&Vf[s][np][lane][0] = u;
        }
        __syncthreads();

        // QK: S = Q @ K^T; one LDS.128 feeds two mmas.
        float sc[8][4];
#pragma unroll
        for (int nt = 0; nt < 8; nt++)
#pragma unroll
            for (int i = 0; i < 4; i++) sc[nt][i] = 0.f;
#pragma unroll
        for (int s = 0; s < 8; s++) {
#pragma unroll
            for (int np = 0; np < 4; np++) {
                uint4 u = *(const uint4*)&Kf[s][np][lane][0];
                mma8(sc[2 * np],     qa[s][0], qa[s][1], qa[s][2], qa[s][3], u.x, u.y);
                mma8(sc[2 * np + 1], qa[s][0], qa[s][1], qa[s][2], qa[s][3], u.z, u.w);
            }
        }

        // Band mask (chunk 0: col >= row; chunk 8: col <= row)
        if (ch == 0) {
#pragma unroll
            for (int nt = 0; nt < 8; nt++) {
                int c0 = 8 * nt + 2 * t;
                if (c0     < rA)     sc[nt][0] = NEG;
                if (c0 + 1 < rA)     sc[nt][1] = NEG;
                if (c0     < rA + 8) sc[nt][2] = NEG;
                if (c0 + 1 < rA + 8) sc[nt][3] = NEG;
            }
        } else if (ch == 8) {
#pragma unroll
            for (int nt = 0; nt < 8; nt++) {
                int c0 = 8 * nt + 2 * t;
                if (c0     > rA)     sc[nt][0] = NEG;
                if (c0 + 1 > rA)     sc[nt][1] = NEG;
                if (c0     > rA + 8) sc[nt][2] = NEG;
                if (c0 + 1 > rA + 8) sc[nt][3] = NEG;
            }
        }

        // Online softmax (rows rA, rA+8; quad reduction over t)
        float vA = NEG, vB = NEG;
#pragma unroll
        for (int nt = 0; nt < 8; nt++) {
            vA = fmaxf(vA, fmaxf(sc[nt][0], sc[nt][1]));
            vB = fmaxf(vB, fmaxf(sc[nt][2], sc[nt][3]));
        }
        vA = fmaxf(vA, __shfl_xor_sync(0xffffffffu, vA, 1));
        vA = fmaxf(vA, __shfl_xor_sync(0xffffffffu, vA, 2));
        vB = fmaxf(vB, __shfl_xor_sync(0xffffffffu, vB, 1));
        vB = fmaxf(vB, __shfl_xor_sync(0xffffffffu, vB, 2));
        float mAn = fmaxf(mA, vA), mBn = fmaxf(mB, vB);
        float sumA = 0.f, sumB = 0.f;
#pragma unroll
        for (int nt = 0; nt < 8; nt++) {
            sc[nt][0] = __expf(sc[nt][0] - mAn);
            sc[nt][1] = __expf(sc[nt][1] - mAn);
            sc[nt][2] = __expf(sc[nt][2] - mBn);
            sc[nt][3] = __expf(sc[nt][3] - mBn);
            sumA += sc[nt][0] + sc[nt][1];
            sumB += sc[nt][2] + sc[nt][3];
        }
        sumA += __shfl_xor_sync(0xffffffffu, sumA, 1);
        sumA += __shfl_xor_sync(0xffffffffu, sumA, 2);
        sumB += __shfl_xor_sync(0xffffffffu, sumB, 1);
        sumB += __shfl_xor_sync(0xffffffffu, sumB, 2);
        float fA = __expf(mA - mAn), fB = __expf(mB - mBn);
        mA = mAn; mB = mBn;
        lA = lA * fA + sumA;
        lB = lB * fB + sumB;
#pragma unroll
        for (int nt = 0; nt < 8; nt++) {
            oacc[nt][0] *= fA; oacc[nt][1] *= fA;
            oacc[nt][2] *= fB; oacc[nt][3] *= fB;
        }

        // PV: O += P @ V.  P stays in registers; one LDS.128 feeds two mmas.
#pragma unroll
        for (int s = 0; s < 8; s++) {
            uint32_t a0 = f2tf(sc[s][0]);
            uint32_t a1 = f2tf(sc[s][2]);
            uint32_t a2 = f2tf(sc[s][1]);
            uint32_t a3 = f2tf(sc[s][3]);
#pragma unroll
            for (int np = 0; np < 4; np++) {
                uint4 u = *(const uint4*)&Vf[s][np][lane][0];
                mma8(oacc[2 * np],     a0, a1, a2, a3, u.x, u.y);
                mma8(oacc[2 * np + 1], a0, a1, a2, a3, u.z, u.w);
            }
        }
    }

    // Epilogue: out_flat[s*2048 + b*512 + h*64 + d]
    float iA = 1.f / lA, iB = 1.f / lB;
    size_t baseA = (size_t)(i0 + rA) * 2048 + (size_t)(bb * 512 + hh * 64);
    size_t baseB = baseA + (size_t)8 * 2048;
#pragma unroll
    for (int nt = 0; nt < 8; nt++) {
        int d = 8 * nt + 2 * t;
        float2 o;
        o.x = oacc[nt][0] * iA; o.y = oacc[nt][1] * iA;
        *(float2*)(out + baseA + d) = o;
        o.x = oacc[nt][2] * iB; o.y = oacc[nt][3] * iB;
        *(float2*)(out + baseB + d) = o;
    }
}

// ---------------------------------------------------------------------------
extern "C" void kernel_launch(void* const* d_in, const int* in_sizes, int n_in,
                              void* d_out, int out_size)
{
    (void)in_sizes; (void)n_in; (void)out_size;
    const float* query = (const float*)d_in[0];
    const float* key   = (const float*)d_in[1];
    const float* value = (const float*)d_in[2];
    const float* Wq = (const float*)d_in[4];
    const float* bq = (const float*)d_in[5];
    const float* Wk = (const float*)d_in[6];
    const float* bk = (const float*)d_in[7];
    const float* Wv = (const float*)d_in[8];
    const float* bv = (const float*)d_in[9];
    float* out = (float*)d_out;

    float *qp, *kp, *vp;
    cudaGetSymbolAddress((void**)&qp, g_q);
    cudaGetSymbolAddress((void**)&kp, g_k);
    cudaGetSymbolAddress((void**)&vp, g_v);

    dim3 gp(EE / 128, (BB * SS) / 128, 3);   // fused Q/K/V projections
    proj_mma<<<gp, 256>>>(query, key, value, Wq, Wk, Wv, bq, bk, bv, qp, kp, vp);

    attn_mma<<<dim3(SS / 64, BHN), 128>>>(out);
}

// round 10
// speedup vs baseline: 1.6131x; 1.0264x over previous
#include <cuda_runtime.h>
#include <math.h>
#include <stdint.h>

#define BB 4
#define SS 4096
#define EE 512
#define HH 8
#define DD 64
#define WW 256
#define BHN (BB*HH)
#define NEG (-1e30f)

// Scratch q/k/v in [b*H+h][s][d] layout (q pre-scaled by 1/sqrt(D))
__device__ float g_q[(size_t)BHN * SS * DD];
__device__ float g_k[(size_t)BHN * SS * DD];
__device__ float g_v[(size_t)BHN * SS * DD];

__device__ __forceinline__ uint32_t f2tf(float f) {
    uint32_t u;
    asm("cvt.rna.tf32.f32 %0, %1;" : "=r"(u) : "f"(f));
    return u;
}

// m16n8k8 tf32 mma, fp32 accumulate. A row-major, B col-major.
__device__ __forceinline__ void mma8(float* c,
                                     uint32_t a0, uint32_t a1, uint32_t a2, uint32_t a3,
                                     uint32_t b0, uint32_t b1) {
    asm volatile(
        "mma.sync.aligned.m16n8k8.row.col.f32.tf32.tf32.f32 "
        "{%0,%1,%2,%3},{%4,%5,%6,%7},{%8,%9},{%0,%1,%2,%3};"
        : "+f"(c[0]), "+f"(c[1]), "+f"(c[2]), "+f"(c[3])
        : "r"(a0), "r"(a1), "r"(a2), "r"(a3), "r"(b0), "r"(b1));
}

// ---------------------------------------------------------------------------
// Fused projection GEMMs (tf32) — unchanged from R9 (known ~239us).
// ---------------------------------------------------------------------------
__global__ __launch_bounds__(256, 2)
void proj_mma(const float* __restrict__ Xq, const float* __restrict__ Xk,
              const float* __restrict__ Xv,
              const float* __restrict__ Wq, const float* __restrict__ Wk,
              const float* __restrict__ Wv,
              const float* __restrict__ bq, const float* __restrict__ bk,
              const float* __restrict__ bv,
              float* __restrict__ Oq, float* __restrict__ Ok,
              float* __restrict__ Ov)
{
    __shared__ uint32_t Ap[8][4][32][4];
    __shared__ uint32_t Bp[8][4][32][4];

    const int z = blockIdx.z;
    const float* X    = (z == 0) ? Xq : (z == 1) ? Xk : Xv;
    const float* Wm   = (z == 0) ? Wq : (z == 1) ? Wk : Wv;
    const float* bias = (z == 0) ? bq : (z == 1) ? bk : bv;
    float*       Out  = (z == 0) ? Oq : (z == 1) ? Ok : Ov;
    const float scale = (z == 0) ? 0.125f : 1.0f;

    const int tid = threadIdx.x;
    const int lane = tid & 31;
    const int w = tid >> 5;
    const int wm = w >> 2;
    const int wn = w & 3;
    const int m0 = blockIdx.y * 128;
    const int n0 = blockIdx.x * 128;
    const int g = lane >> 2;
    const int t = lane & 3;

    float acc[4][4][4];
#pragma unroll
    for (int mt = 0; mt < 4; mt++)
#pragma unroll
        for (int nt = 0; nt < 4; nt++)
#pragma unroll
            for (int i = 0; i < 4; i++) acc[mt][nt][i] = 0.f;

    const float* aBase[4];
    const float* bBase[4];
#pragma unroll
    for (int p = 0; p < 4; p++) {
        int pair = w * 4 + p;
        int mt = pair >> 2, s = pair & 3;
        aBase[p] = X + (size_t)(m0 + mt * 16 + g) * EE + 8 * s + 2 * t;
    }
#pragma unroll
    for (int p = 0; p < 4; p++) {
        int slot = w * 4 + p;
        int np = slot >> 2, s = slot & 3;
        bBase[p] = Wm + (size_t)(n0 + np * 16 + g) * EE + 8 * s + 2 * t;
    }

    float2 pa0[4], pa1[4], pb0[4], pb1[4];
#pragma unroll
    for (int p = 0; p < 4; p++) {
        pa0[p] = *(const float2*)(aBase[p]);
        pa1[p] = *(const float2*)(aBase[p] + 8 * EE);
        pb0[p] = *(const float2*)(bBase[p]);
        pb1[p] = *(const float2*)(bBase[p] + 8 * EE);
    }

    for (int kc = 0; kc < 16; kc++) {
#pragma unroll
        for (int p = 0; p < 4; p++) {
            int pair = w * 4 + p;
            int mt = pair >> 2, s = pair & 3;
            uint4 u;
            u.x = f2tf(pa0[p].x);
            u.y = f2tf(pa1[p].x);
            u.z = f2tf(pa0[p].y);
            u.w = f2tf(pa1[p].y);
            *(uint4*)&Ap[mt][s][lane][0] = u;
        }
#pragma unroll
        for (int p = 0; p < 4; p++) {
            int slot = w * 4 + p;
            int np = slot >> 2, s = slot & 3;
            uint4 u;
            u.x = f2tf(pb0[p].x);
            u.y = f2tf(pb0[p].y);
            u.z = f2tf(pb1[p].x);
            u.w = f2tf(pb1[p].y);
            *(uint4*)&Bp[np][s][lane][0] = u;
        }
        __syncthreads();

        if (kc + 1 < 16) {
            const int koff = (kc + 1) * 32;
#pragma unroll
            for (int p = 0; p < 4; p++) {
                pa0[p] = *(const float2*)(aBase[p] + koff);
                pa1[p] = *(const float2*)(aBase[p] + koff + 8 * EE);
                pb0[p] = *(const float2*)(bBase[p] + koff);
                pb1[p] = *(const float2*)(bBase[p] + koff + 8 * EE);
            }
        }

#pragma unroll
        for (int s = 0; s < 4; s++) {
            uint4 bf0 = *(const uint4*)&Bp[wn * 2 + 0][s][lane][0];
            uint4 bf1 = *(const uint4*)&Bp[wn * 2 + 1][s][lane][0];
#pragma unroll
            for (int mt = 0; mt < 4; mt++) {
                uint4 af = *(const uint4*)&Ap[wm * 4 + mt][s][lane][0];
                mma8(acc[mt][0], af.x, af.y, af.z, af.w, bf0.x, bf0.y);
                mma8(acc[mt][1], af.x, af.y, af.z, af.w, bf0.z, bf0.w);
                mma8(acc[mt][2], af.x, af.y, af.z, af.w, bf1.x, bf1.y);
                mma8(acc[mt][3], af.x, af.y, af.z, af.w, bf1.z, bf1.w);
            }
        }
        __syncthreads();
    }

#pragma unroll
    for (int mt = 0; mt < 4; mt++) {
        int r0 = m0 + wm * 64 + mt * 16 + g;
        int r1 = r0 + 8;
        int b0i = r0 >> 12, s0i = r0 & (SS - 1);
        int b1i = r1 >> 12, s1i = r1 & (SS - 1);
#pragma unroll
        for (int nt = 0; nt < 4; nt++) {
            int n = n0 + wn * 32 + nt * 8 + 2 * t;
            int h = n >> 6, d = n & 63;
            float2 bi = *(const float2*)(bias + n);
            float2 o;
            o.x = (acc[mt][nt][0] + bi.x) * scale;
            o.y = (acc[mt][nt][1] + bi.y) * scale;
            *(float2*)(&Out[((size_t)(b0i * HH + h) * SS + s0i) * DD + d]) = o;
            o.x = (acc[mt][nt][2] + bi.x) * scale;
            o.y = (acc[mt][nt][3] + bi.y) * scale;
            *(float2*)(&Out[((size_t)(b1i * HH + h) * SS + s1i) * DD + d]) = o;
        }
    }
}

// ---------------------------------------------------------------------------
// Band attention (tf32 mma.sync), 128-query-row blocks:
// 4 warps, warp w owns rows [32w, 32w+32) as 2 m-tiles.  Q staged once to
// smem (fragment-packed); K/V staged per 64-key chunk (10 chunks, window
// |i-j|<=256).  One K/V LDS.128 feeds 4 mmas (2 m-tiles x 2 nt).
// P stays in registers (C-frag == A-frag under j-permutation).
// Dynamic smem 64KB: Qf 32KB | Kf 16KB | Vf 16KB.
// ---------------------------------------------------------------------------
#define QIDX(s, mq, ln) ((((s) * 8 + (mq)) * 32 + (ln)) * 4)
#define KIDX(s, np, ln) ((((s) * 4 + (np)) * 32 + (ln)) * 4)
#define SMEM_ATTN (64 * 1024)

__global__ __launch_bounds__(128)
void attn_mma(float* __restrict__ out)
{
    extern __shared__ uint32_t dsm[];
    uint32_t* Qf = dsm;                 // [s][mq][lane][4], mq = 0..7
    uint32_t* Kf = dsm + 8192;          // [s][np][lane][4], np = 0..3
    uint32_t* Vf = dsm + 12288;         // [s][np][lane][4]

    const int bh = blockIdx.y;
    const int bb = bh >> 3;
    const int hh = bh & 7;
    const int i0 = blockIdx.x * 128;
    const int tid = threadIdx.x;
    const int w = tid >> 5;
    const int lane = tid & 31;
    const int g = lane >> 2;
    const int t = lane & 3;

    const float* qg = g_q + (size_t)bh * SS * DD;
    const float* kg = g_k + (size_t)bh * SS * DD;
    const float* vg = g_v + (size_t)bh * SS * DD;

    // Stage Q once: 64 (s,mq) slots, 16 per warp (its own mq = 2w, 2w+1).
#pragma unroll
    for (int p = 0; p < 16; p++) {
        int slot = w * 16 + p;
        int mq = slot >> 3, s = slot & 7;
        const float* r0 = qg + (size_t)(i0 + 16 * mq + g) * DD + 8 * s + 2 * t;
        float2 x0 = *(const float2*)r0;
        float2 x1 = *(const float2*)(r0 + 8 * DD);
        uint4 u;
        u.x = f2tf(x0.x); u.y = f2tf(x1.x);
        u.z = f2tf(x0.y); u.w = f2tf(x1.y);
        *(uint4*)&Qf[QIDX(s, mq, lane)] = u;
    }

    float oacc[2][8][4];
#pragma unroll
    for (int mt = 0; mt < 2; mt++)
#pragma unroll
        for (int nt = 0; nt < 8; nt++)
#pragma unroll
            for (int i = 0; i < 4; i++) oacc[mt][nt][i] = 0.f;
    float mA[2] = {NEG, NEG}, mB[2] = {NEG, NEG};
    float lA[2] = {0.f, 0.f}, lB[2] = {0.f, 0.f};

    for (int cg = 0; cg < 10; cg++) {
        int j0 = i0 - WW + cg * 64;
        if (j0 < 0 || j0 >= SS) continue;   // uniform per block

        __syncthreads();   // prior reads done before restage (also covers Q)

        const float* kp = kg + (size_t)j0 * DD;
        const float* vp = vg + (size_t)j0 * DD;
        // K packed slots: 32 (s,np), 8 per warp; 2 LDG.64 + STS.128.
#pragma unroll
        for (int p = 0; p < 8; p++) {
            int slot = w * 8 + p;
            int np = slot >> 3, s = slot & 7;
            const float* r0 = kp + (size_t)(16 * np + g) * DD + 8 * s + 2 * t;
            float2 x0 = *(const float2*)r0;
            float2 x1 = *(const float2*)(r0 + 8 * DD);
            uint4 u;
            u.x = f2tf(x0.x); u.y = f2tf(x0.y);
            u.z = f2tf(x1.x); u.w = f2tf(x1.y);
            *(uint4*)&Kf[KIDX(s, np, lane)] = u;
        }
        // V packed slots: 4 LDG.32 + STS.128.
#pragma unroll
        for (int p = 0; p < 8; p++) {
            int slot = w * 8 + p;
            int np = slot >> 3, s = slot & 7;
            const float* r0 = vp + (size_t)(8 * s + 2 * t) * DD;
            const float* r1 = r0 + DD;
            uint4 u;
            u.x = f2tf(r0[16 * np + g]);
            u.y = f2tf(r1[16 * np + g]);
            u.z = f2tf(r0[16 * np + 8 + g]);
            u.w = f2tf(r1[16 * np + 8 + g]);
            *(uint4*)&Vf[KIDX(s, np, lane)] = u;
        }
        __syncthreads();

        // QK: S = Q @ K^T  (32 rows x 64 cols per warp)
        float sc[2][8][4];
#pragma unroll
        for (int mt = 0; mt < 2; mt++)
#pragma unroll
            for (int nt = 0; nt < 8; nt++)
#pragma unroll
                for (int i = 0; i < 4; i++) sc[mt][nt][i] = 0.f;
#pragma unroll
        for (int s = 0; s < 8; s++) {
            uint4 q0 = *(const uint4*)&Qf[QIDX(s, 2 * w + 0, lane)];
            uint4 q1 = *(const uint4*)&Qf[QIDX(s, 2 * w + 1, lane)];
#pragma unroll
            for (int np = 0; np < 4; np++) {
                uint4 u = *(const uint4*)&Kf[KIDX(s, np, lane)];
                mma8(sc[0][2 * np],     q0.x, q0.y, q0.z, q0.w, u.x, u.y);
                mma8(sc[0][2 * np + 1], q0.x, q0.y, q0.z, q0.w, u.z, u.w);
                mma8(sc[1][2 * np],     q1.x, q1.y, q1.z, q1.w, u.x, u.y);
                mma8(sc[1][2 * np + 1], q1.x, q1.y, q1.z, q1.w, u.z, u.w);
            }
        }

        // Band mask: valid iff 0 <= 64*cg + col - row <= 512.
        if (cg <= 1) {
#pragma unroll
            for (int mt = 0; mt < 2; mt++) {
                int lo = 32 * w + 16 * mt + g - 64 * cg;   // col >= lo valid
#pragma unroll
                for (int nt = 0; nt < 8; nt++) {
                    int c0 = 8 * nt + 2 * t;
                    if (c0     < lo)     sc[mt][nt][0] = NEG;
                    if (c0 + 1 < lo)     sc[mt][nt][1] = NEG;
                    if (c0     < lo + 8) sc[mt][nt][2] = NEG;
                    if (c0 + 1 < lo + 8) sc[mt][nt][3] = NEG;
                }
            }
        } else if (cg >= 8) {
#pragma unroll
            for (int mt = 0; mt < 2; mt++) {
                int hi = 32 * w + 16 * mt + g + 512 - 64 * cg;  // col <= hi
#pragma unroll
                for (int nt = 0; nt < 8; nt++) {
                    int c0 = 8 * nt + 2 * t;
                    if (c0     > hi)     sc[mt][nt][0] = NEG;
                    if (c0 + 1 > hi)     sc[mt][nt][1] = NEG;
                    if (c0     > hi + 8) sc[mt][nt][2] = NEG;
                    if (c0 + 1 > hi + 8) sc[mt][nt][3] = NEG;
                }
            }
        }

        // Online softmax per m-tile (max clamped at -1e20 so fully-masked
        // chunks contribute exactly 0: exp(-1e30 + 1e20) == 0).
#pragma unroll
        for (int mt = 0; mt < 2; mt++) {
            float vAx = NEG, vBx = NEG;
#pragma unroll
            for (int nt = 0; nt < 8; nt++) {
                vAx = fmaxf(vAx, fmaxf(sc[mt][nt][0], sc[mt][nt][1]));
                vBx = fmaxf(vBx, fmaxf(sc[mt][nt][2], sc[mt][nt][3]));
            }
            vAx = fmaxf(vAx, __shfl_xor_sync(0xffffffffu, vAx, 1));
            vAx = fmaxf(vAx, __shfl_xor_sync(0xffffffffu, vAx, 2));
            vBx = fmaxf(vBx, __shfl_xor_sync(0xffffffffu, vBx, 1));
            vBx = fmaxf(vBx, __shfl_xor_sync(0xffffffffu, vBx, 2));
            float mAn = fmaxf(fmaxf(mA[mt], vAx), -1e20f);
            float mBn = fmaxf(fmaxf(mB[mt], vBx), -1e20f);
            float sumA = 0.f, sumB = 0.f;
#pragma unroll
            for (int nt = 0; nt < 8; nt++) {
                sc[mt][nt][0] = __expf(sc[mt][nt][0] - mAn);
                sc[mt][nt][1] = __expf(sc[mt][nt][1] - mAn);
                sc[mt][nt][2] = __expf(sc[mt][nt][2] - mBn);
                sc[mt][nt][3] = __expf(sc[mt][nt][3] - mBn);
                sumA += sc[mt][nt][0] + sc[mt][nt][1];
                sumB += sc[mt][nt][2] + sc[mt][nt][3];
            }
            sumA += __shfl_xor_sync(0xffffffffu, sumA, 1);
            sumA += __shfl_xor_sync(0xffffffffu, sumA, 2);
            sumB += __shfl_xor_sync(0xffffffffu, sumB, 1);
            sumB += __shfl_xor_sync(0xffffffffu, sumB, 2);
            float fA = __expf(mA[mt] - mAn), fB = __expf(mB[mt] - mBn);
            mA[mt] = mAn; mB[mt] = mBn;
            lA[mt] = lA[mt] * fA + sumA;
            lB[mt] = lB[mt] * fB + sumB;
#pragma unroll
            for (int nt = 0; nt < 8; nt++) {
                oacc[mt][nt][0] *= fA; oacc[mt][nt][1] *= fA;
                oacc[mt][nt][2] *= fB; oacc[mt][nt][3] *= fB;
            }
        }

        // PV: O += P @ V.  One V LDS.128 feeds both m-tiles (4 mmas).
#pragma unroll
        for (int s = 0; s < 8; s++) {
            uint32_t a[2][4];
#pragma unroll
            for (int mt = 0; mt < 2; mt++) {
                a[mt][0] = f2tf(sc[mt][s][0]);
                a[mt][1] = f2tf(sc[mt][s][2]);
                a[mt][2] = f2tf(sc[mt][s][1]);
                a[mt][3] = f2tf(sc[mt][s][3]);
            }
#pragma unroll
            for (int np = 0; np < 4; np++) {
                uint4 u = *(const uint4*)&Vf[KIDX(s, np, lane)];
                mma8(oacc[0][2 * np],     a[0][0], a[0][1], a[0][2], a[0][3], u.x, u.y);
                mma8(oacc[0][2 * np + 1], a[0][0], a[0][1], a[0][2], a[0][3], u.z, u.w);
                mma8(oacc[1][2 * np],     a[1][0], a[1][1], a[1][2], a[1][3], u.x, u.y);
                mma8(oacc[1][2 * np + 1], a[1][0], a[1][1], a[1][2], a[1][3], u.z, u.w);
            }
        }
    }

    // Epilogue: out_flat[s*2048 + b*512 + h*64 + d]
#pragma unroll
    for (int mt = 0; mt < 2; mt++) {
        float iA = 1.f / lA[mt], iB = 1.f / lB[mt];
        size_t baseA = (size_t)(i0 + 32 * w + 16 * mt + g) * 2048
                     + (size_t)(bb * 512 + hh * 64);
        size_t baseB = baseA + (size_t)8 * 2048;
#pragma unroll
        for (int nt = 0; nt < 8; nt++) {
            int d = 8 * nt + 2 * t;
            float2 o;
            o.x = oacc[mt][nt][0] * iA; o.y = oacc[mt][nt][1] * iA;
            *(float2*)(out + baseA + d) = o;
            o.x = oacc[mt][nt][2] * iB; o.y = oacc[mt][nt][3] * iB;
            *(float2*)(out + baseB + d) = o;
        }
    }
}

// ---------------------------------------------------------------------------
extern "C" void kernel_launch(void* const* d_in, const int* in_sizes, int n_in,
                              void* d_out, int out_size)
{
    (void)in_sizes; (void)n_in; (void)out_size;
    const float* query = (const float*)d_in[0];
    const float* key   = (const float*)d_in[1];
    const float* value = (const float*)d_in[2];
    const float* Wq = (const float*)d_in[4];
    const float* bq = (const float*)d_in[5];
    const float* Wk = (const float*)d_in[6];
    const float* bk = (const float*)d_in[7];
    const float* Wv = (const float*)d_in[8];
    const float* bv = (const float*)d_in[9];
    float* out = (float*)d_out;

    float *qp, *kp, *vp;
    cudaGetSymbolAddress((void**)&qp, g_q);
    cudaGetSymbolAddress((void**)&kp, g_k);
    cudaGetSymbolAddress((void**)&vp, g_v);

    dim3 gp(EE / 128, (BB * SS) / 128, 3);   // fused Q/K/V projections
    proj_mma<<<gp, 256>>>(query, key, value, Wq, Wk, Wv, bq, bk, bv, qp, kp, vp);

    static int smem_set = 0;
    if (!smem_set) {
        cudaFuncSetAttribute(attn_mma,
                             cudaFuncAttributeMaxDynamicSharedMemorySize,
                             SMEM_ATTN);
        smem_set = 1;
    }
    attn_mma<<<dim3(SS / 128, BHN), 128, SMEM_ATTN>>>(out);
}